// round 1
// baseline (speedup 1.0000x reference)
#include <cuda_runtime.h>
#include <cstdint>

#define N_NODES 100000

// ---------------- scratch (static device globals; no runtime alloc) ----------------
__device__ float g_dinv[N_NODES];          // degree -> rsqrt(degree)
__device__ float g_u  [N_NODES * 64];      // transformed + dinv[row]-scaled features
__device__ float g_agg[N_NODES * 64];      // edge aggregation buffer
__device__ float g_f1 [N_NODES * 64];
__device__ float g_f2 [N_NODES * 32];
__device__ float g_f3 [N_NODES * 16];

static inline int cdiv(long long a, long long b) { return (int)((a + b - 1) / b); }

// ---------------- degree / dinv ----------------
__global__ void k_init_deg()
{
    int i = blockIdx.x * blockDim.x + threadIdx.x;
    if (i < N_NODES) g_dinv[i] = 1.0f;   // self-loop contributes 1
}

__global__ void k_count_deg(const int* __restrict__ col, int E)
{
    int e = blockIdx.x * blockDim.x + threadIdx.x;
    if (e < E) atomicAdd(&g_dinv[col[e]], 1.0f);
}

__global__ void k_make_dinv()
{
    int i = blockIdx.x * blockDim.x + threadIdx.x;
    if (i < N_NODES) g_dinv[i] = rsqrtf(g_dinv[i]);   // deg >= 1 always
}

// ---------------- GEMM: u = (X @ W) * dinv[node], also zero agg ----------------
// BN=64 nodes/block, 256 threads, thread tile 4 nodes x (F/16) outputs.
template<int K, int F, int LAYER>
__global__ void __launch_bounds__(256) k_gemm(const float* __restrict__ Xp,
                                              const float* __restrict__ W)
{
    constexpr int BN   = 64;
    constexpr int KC   = (K > 64) ? 64 : K;
    constexpr int TN   = F / 16;          // 4, 2, 1
    constexpr int XPAD = BN + 4;          // 68 (keeps float4 alignment, breaks conflicts)

    __shared__ __align__(16) float xs[KC * XPAD];
    __shared__ __align__(16) float ws[KC * F];

    const float* X = (LAYER == 1) ? Xp : (LAYER == 2 ? g_f1 : g_f2);

    const int tid   = threadIdx.x;
    const int node0 = blockIdx.x * BN;
    const int tn    = tid & 15;
    const int tm    = tid >> 4;
    const int nloc  = tm * 4;
    const int ob    = tn * TN;

    float acc[4][TN];
#pragma unroll
    for (int m = 0; m < 4; m++)
#pragma unroll
        for (int j = 0; j < TN; j++) acc[m][j] = 0.f;

    for (int kc = 0; kc < K; kc += KC) {
        // stage W chunk
        for (int i = tid; i < KC * F; i += 256)
            ws[i] = W[kc * F + i];
        // stage X tile transposed: xs[k][node]
        for (int i = tid; i < BN * KC; i += 256) {
            int r = i / KC, c = i % KC;
            int nr = node0 + r;
            xs[c * XPAD + r] = (nr < N_NODES) ? X[(size_t)nr * K + kc + c] : 0.f;
        }
        __syncthreads();

#pragma unroll 8
        for (int k = 0; k < KC; k++) {
            float4 xv = *(const float4*)&xs[k * XPAD + nloc];
#pragma unroll
            for (int j = 0; j < TN; j++) {
                float w = ws[k * F + ob + j];
                acc[0][j] = fmaf(xv.x, w, acc[0][j]);
                acc[1][j] = fmaf(xv.y, w, acc[1][j]);
                acc[2][j] = fmaf(xv.z, w, acc[2][j]);
                acc[3][j] = fmaf(xv.w, w, acc[3][j]);
            }
        }
        __syncthreads();
    }

#pragma unroll
    for (int m = 0; m < 4; m++) {
        int node = node0 + nloc + m;
        if (node < N_NODES) {
            float s = g_dinv[node];
#pragma unroll
            for (int j = 0; j < TN; j++) {
                g_u  [(size_t)node * F + ob + j] = acc[m][j] * s;
                g_agg[(size_t)node * F + ob + j] = 0.f;
            }
        }
    }
}

// ---------------- edge scatter: agg[col] += u[row]  (vector red.v4) ----------------
template<int F>
__global__ void __launch_bounds__(256) k_scatter(const int* __restrict__ row,
                                                 const int* __restrict__ col,
                                                 int E)
{
    constexpr int L  = F / 4;                           // float4 lanes per edge: 16/8/4
    constexpr int SH = (F == 64) ? 4 : ((F == 32) ? 3 : 2);

    long long idx = (long long)blockIdx.x * blockDim.x + threadIdx.x;
    long long e   = idx >> SH;
    int lane      = threadIdx.x & 31;
    int sub       = lane & (L - 1);
    int leader    = lane & ~(L - 1);

    long long ec = (e < E) ? e : (long long)(E - 1);
    int r = 0, c = 0;
    if (sub == 0) { r = __ldg(row + ec); c = __ldg(col + ec); }
    r = __shfl_sync(0xffffffffu, r, leader);
    c = __shfl_sync(0xffffffffu, c, leader);

    float4 v = __ldg((const float4*)g_u + (size_t)r * L + sub);

    if (e < E) {
        float4* dst = (float4*)g_agg + (size_t)c * L + sub;
        asm volatile("red.global.add.v4.f32 [%0], {%1,%2,%3,%4};"
                     :: "l"(dst), "f"(v.x), "f"(v.y), "f"(v.z), "f"(v.w)
                     : "memory");
    }
}

// ---------------- finalize: f = relu(dinv[i]*(agg + u) + b) ----------------
template<int F, int LAYER>
__global__ void __launch_bounds__(256) k_finalize(const float* __restrict__ b)
{
    constexpr int F4 = F / 4;
    int idx = blockIdx.x * blockDim.x + threadIdx.x;
    if (idx >= N_NODES * F4) return;
    int i = idx / F4;
    int j = idx - i * F4;

    float  s  = g_dinv[i];
    float4 a  = ((const float4*)g_agg)[idx];
    float4 u  = ((const float4*)g_u)[idx];
    float4 bb = __ldg((const float4*)b + j);

    float4 r;
    r.x = fmaxf(fmaf(s, a.x + u.x, bb.x), 0.f);
    r.y = fmaxf(fmaf(s, a.y + u.y, bb.y), 0.f);
    r.z = fmaxf(fmaf(s, a.z + u.z, bb.z), 0.f);
    r.w = fmaxf(fmaf(s, a.w + u.w, bb.w), 0.f);

    float* outp = (LAYER == 1) ? g_f1 : (LAYER == 2 ? g_f2 : g_f3);
    ((float4*)outp)[idx] = r;
}

// ---------------- head: out = relu([f1|f2|f3] @ Wfc + bfc) ----------------
__global__ void __launch_bounds__(256) k_head(const float* __restrict__ Wfc,
                                              const float* __restrict__ bfc,
                                              float* __restrict__ out)
{
    __shared__ float wsh[112 * 16];
    __shared__ float fs [16 * 112];
    __shared__ float bs [16];

    const int tid   = threadIdx.x;
    const int node0 = blockIdx.x * 16;

    for (int i = tid; i < 112 * 16; i += 256) wsh[i] = Wfc[i];
    if (tid < 16) bs[tid] = bfc[tid];

    for (int i = tid; i < 16 * 64; i += 256) {
        int ln = i >> 6, k = i & 63; int n = node0 + ln;
        fs[ln * 112 + k] = (n < N_NODES) ? g_f1[(size_t)n * 64 + k] : 0.f;
    }
    for (int i = tid; i < 16 * 32; i += 256) {
        int ln = i >> 5, k = i & 31; int n = node0 + ln;
        fs[ln * 112 + 64 + k] = (n < N_NODES) ? g_f2[(size_t)n * 32 + k] : 0.f;
    }
    for (int i = tid; i < 16 * 16; i += 256) {
        int ln = i >> 4, k = i & 15; int n = node0 + ln;
        fs[ln * 112 + 96 + k] = (n < N_NODES) ? g_f3[(size_t)n * 16 + k] : 0.f;
    }
    __syncthreads();

    const int ln = tid >> 4, j = tid & 15;
    float acc = bs[j];
#pragma unroll
    for (int k = 0; k < 112; k++)
        acc = fmaf(fs[ln * 112 + k], wsh[k * 16 + j], acc);

    int n = node0 + ln;
    if (n < N_NODES) out[(size_t)n * 16 + j] = fmaxf(acc, 0.f);
}

// ---------------- launch ----------------
extern "C" void kernel_launch(void* const* d_in, const int* in_sizes, int n_in,
                              void* d_out, int out_size)
{
    const int*   edges = (const int*)d_in[0];
    const float* feats = (const float*)d_in[1];
    const float* W1    = (const float*)d_in[2];
    const float* b1    = (const float*)d_in[3];
    const float* W2    = (const float*)d_in[4];
    const float* b2    = (const float*)d_in[5];
    const float* W3    = (const float*)d_in[6];
    const float* b3    = (const float*)d_in[7];
    const float* Wfc   = (const float*)d_in[8];
    const float* bfc   = (const float*)d_in[9];
    float* out = (float*)d_out;

    const int E   = in_sizes[0] / 2;
    const int* row = edges;
    const int* col = edges + E;

    // degree -> dinv
    k_init_deg <<<cdiv(N_NODES, 256), 256>>>();
    k_count_deg<<<cdiv(E, 256), 256>>>(col, E);
    k_make_dinv<<<cdiv(N_NODES, 256), 256>>>();

    const int gemm_grid = cdiv(N_NODES, 64);

    // layer 1: 128 -> 64
    k_gemm<128, 64, 1><<<gemm_grid, 256>>>(feats, W1);
    k_scatter<64><<<cdiv((long long)E * 16, 256), 256>>>(row, col, E);
    k_finalize<64, 1><<<cdiv((long long)N_NODES * 16, 256), 256>>>(b1);

    // layer 2: 64 -> 32
    k_gemm<64, 32, 2><<<gemm_grid, 256>>>(nullptr, W2);
    k_scatter<32><<<cdiv((long long)E * 8, 256), 256>>>(row, col, E);
    k_finalize<32, 2><<<cdiv((long long)N_NODES * 8, 256), 256>>>(b2);

    // layer 3: 32 -> 16
    k_gemm<32, 16, 3><<<gemm_grid, 256>>>(nullptr, W3);
    k_scatter<16><<<cdiv((long long)E * 4, 256), 256>>>(row, col, E);
    k_finalize<16, 3><<<cdiv((long long)N_NODES * 4, 256), 256>>>(b3);

    // dense head
    k_head<<<cdiv(N_NODES, 16), 256>>>(Wfc, bfc, out);
}

// round 2
// speedup vs baseline: 1.4180x; 1.4180x over previous
#include <cuda_runtime.h>
#include <cstdint>

#define N_NODES 100000
#define MAX_E   3200000
#define NB_SCAN ((N_NODES + 1023) / 1024)   // 98

// ---------------- scratch (static device globals) ----------------
__device__ int   g_deg [N_NODES];
__device__ int   g_scan[N_NODES];
__device__ int   g_bsum[NB_SCAN];
__device__ int   g_bpre[NB_SCAN];
__device__ int   g_offs[N_NODES + 1];
__device__ int   g_cur [N_NODES];
__device__ int   g_srow[MAX_E];            // row indices sorted by col (CSR)
__device__ float g_dinv[N_NODES];
__device__ float g_u  [N_NODES * 64];      // (X@W) * dinv[node]
__device__ float g_f1 [N_NODES * 64];
__device__ float g_f2 [N_NODES * 32];
__device__ float g_f3 [N_NODES * 16];

static inline int cdiv(long long a, long long b) { return (int)((a + b - 1) / b); }

// ---------------- degree ----------------
__global__ void k_zero_deg()
{
    int i = blockIdx.x * blockDim.x + threadIdx.x;
    if (i < N_NODES) g_deg[i] = 0;
}

__global__ void k_count_deg(const int* __restrict__ col, int E)
{
    int e = blockIdx.x * blockDim.x + threadIdx.x;
    if (e < E) atomicAdd(&g_deg[col[e]], 1);
}

// ---------------- exclusive scan of degrees -> CSR offsets ----------------
__global__ void __launch_bounds__(1024) k_scan_block()
{
    __shared__ int s[1024];
    int i = blockIdx.x * 1024 + threadIdx.x;
    int v = (i < N_NODES) ? g_deg[i] : 0;
    s[threadIdx.x] = v;
    __syncthreads();
#pragma unroll
    for (int off = 1; off < 1024; off <<= 1) {
        int t = (threadIdx.x >= off) ? s[threadIdx.x - off] : 0;
        __syncthreads();
        s[threadIdx.x] += t;
        __syncthreads();
    }
    if (i < N_NODES) g_scan[i] = s[threadIdx.x];
    if (threadIdx.x == 1023) g_bsum[blockIdx.x] = s[1023];
}

__global__ void __launch_bounds__(128) k_scan_tops()
{
    __shared__ int s[128];
    int tid = threadIdx.x;
    int v = (tid < NB_SCAN) ? g_bsum[tid] : 0;
    s[tid] = v;
    __syncthreads();
#pragma unroll
    for (int off = 1; off < 128; off <<= 1) {
        int t = (tid >= off) ? s[tid - off] : 0;
        __syncthreads();
        s[tid] += t;
        __syncthreads();
    }
    if (tid < NB_SCAN) g_bpre[tid] = s[tid] - v;   // exclusive
}

__global__ void k_scan_final(int E)
{
    int i = blockIdx.x * blockDim.x + threadIdx.x;
    if (i >= N_NODES) return;
    int d    = g_deg[i];
    int excl = g_scan[i] - d + g_bpre[i >> 10];
    g_offs[i] = excl;
    g_cur [i] = excl;
    g_dinv[i] = rsqrtf((float)(d + 1));            // +1 self loop
    if (i == N_NODES - 1) g_offs[N_NODES] = excl + d;
}

__global__ void k_csr_fill(const int* __restrict__ row, const int* __restrict__ col, int E)
{
    int e = blockIdx.x * blockDim.x + threadIdx.x;
    if (e < E) {
        int pos = atomicAdd(&g_cur[col[e]], 1);
        g_srow[pos] = row[e];
    }
}

// ---------------- GEMM: u = (X @ W) * dinv[node] ----------------
template<int K, int F, int LAYER>
__global__ void __launch_bounds__(256) k_gemm(const float* __restrict__ Xp,
                                              const float* __restrict__ W)
{
    constexpr int BN   = 64;
    constexpr int KC   = (K > 64) ? 64 : K;
    constexpr int TN   = F / 16;          // 4, 2, 1
    constexpr int XPAD = BN + 4;

    __shared__ __align__(16) float xs[KC * XPAD];
    __shared__ __align__(16) float ws[KC * F];

    const float* X = (LAYER == 1) ? Xp : (LAYER == 2 ? g_f1 : g_f2);

    const int tid   = threadIdx.x;
    const int node0 = blockIdx.x * BN;
    const int tn    = tid & 15;
    const int tm    = tid >> 4;
    const int nloc  = tm * 4;
    const int ob    = tn * TN;

    float acc[4][TN];
#pragma unroll
    for (int m = 0; m < 4; m++)
#pragma unroll
        for (int j = 0; j < TN; j++) acc[m][j] = 0.f;

    for (int kc = 0; kc < K; kc += KC) {
        for (int i = tid; i < KC * F; i += 256)
            ws[i] = W[kc * F + i];
        for (int i = tid; i < BN * KC; i += 256) {
            int r = i / KC, c = i % KC;
            int nr = node0 + r;
            xs[c * XPAD + r] = (nr < N_NODES) ? X[(size_t)nr * K + kc + c] : 0.f;
        }
        __syncthreads();

#pragma unroll 8
        for (int k = 0; k < KC; k++) {
            float4 xv = *(const float4*)&xs[k * XPAD + nloc];
            if constexpr (TN == 4) {
                float4 wv = *(const float4*)&ws[k * F + ob];
                float wj[4] = {wv.x, wv.y, wv.z, wv.w};
#pragma unroll
                for (int j = 0; j < 4; j++) {
                    acc[0][j] = fmaf(xv.x, wj[j], acc[0][j]);
                    acc[1][j] = fmaf(xv.y, wj[j], acc[1][j]);
                    acc[2][j] = fmaf(xv.z, wj[j], acc[2][j]);
                    acc[3][j] = fmaf(xv.w, wj[j], acc[3][j]);
                }
            } else if constexpr (TN == 2) {
                float2 wv = *(const float2*)&ws[k * F + ob];
                float wj[2] = {wv.x, wv.y};
#pragma unroll
                for (int j = 0; j < 2; j++) {
                    acc[0][j] = fmaf(xv.x, wj[j], acc[0][j]);
                    acc[1][j] = fmaf(xv.y, wj[j], acc[1][j]);
                    acc[2][j] = fmaf(xv.z, wj[j], acc[2][j]);
                    acc[3][j] = fmaf(xv.w, wj[j], acc[3][j]);
                }
            } else {
                float w = ws[k * F + ob];
                acc[0][0] = fmaf(xv.x, w, acc[0][0]);
                acc[1][0] = fmaf(xv.y, w, acc[1][0]);
                acc[2][0] = fmaf(xv.z, w, acc[2][0]);
                acc[3][0] = fmaf(xv.w, w, acc[3][0]);
            }
        }
        __syncthreads();
    }

#pragma unroll
    for (int m = 0; m < 4; m++) {
        int node = node0 + nloc + m;
        if (node < N_NODES) {
            float s = g_dinv[node];
#pragma unroll
            for (int j = 0; j < TN; j++)
                g_u[(size_t)node * F + ob + j] = acc[m][j] * s;
        }
    }
}

// ---------------- fused gather + finalize: f = relu(dinv*(sum_nb u + u_self) + b) ----------------
template<int F, int LAYER>
__global__ void __launch_bounds__(256) k_gather(const float* __restrict__ b)
{
    constexpr int VPL = (F == 64) ? 2 : 1;   // floats per lane
    constexpr int LPN = F / VPL;             // lanes per node: 32, 32, 16
    constexpr int NPW = 32 / LPN;            // nodes per warp: 1, 1, 2

    const int warp = (blockIdx.x * blockDim.x + threadIdx.x) >> 5;
    const int lane = threadIdx.x & 31;
    const int sub  = lane / LPN;
    const int cl   = lane - sub * LPN;
    const int node = warp * NPW + sub;
    if (node >= N_NODES) return;

    const unsigned mask = (LPN == 32) ? 0xffffffffu : (0xffffu << (sub * 16));
    const int start = g_offs[node];
    const int end   = g_offs[node + 1];

    float a0[VPL], a1[VPL], a2[VPL], a3[VPL];
#pragma unroll
    for (int v = 0; v < VPL; v++) { a0[v] = a1[v] = a2[v] = a3[v] = 0.f; }

    for (int base = start; base < end; base += LPN) {
        const int m = min(LPN, end - base);
        int rp = (cl < m) ? __ldg(g_srow + base + cl) : 0;

        int i = 0;
        for (; i + 4 <= m; i += 4) {
            int r0 = __shfl_sync(mask, rp, sub * LPN + i + 0);
            int r1 = __shfl_sync(mask, rp, sub * LPN + i + 1);
            int r2 = __shfl_sync(mask, rp, sub * LPN + i + 2);
            int r3 = __shfl_sync(mask, rp, sub * LPN + i + 3);
            if constexpr (VPL == 2) {
                const float2* up = (const float2*)g_u;
                float2 v0 = __ldg(up + (size_t)r0 * 32 + cl);
                float2 v1 = __ldg(up + (size_t)r1 * 32 + cl);
                float2 v2 = __ldg(up + (size_t)r2 * 32 + cl);
                float2 v3 = __ldg(up + (size_t)r3 * 32 + cl);
                a0[0] += v0.x; a0[1] += v0.y;
                a1[0] += v1.x; a1[1] += v1.y;
                a2[0] += v2.x; a2[1] += v2.y;
                a3[0] += v3.x; a3[1] += v3.y;
            } else {
                a0[0] += __ldg(g_u + (size_t)r0 * F + cl);
                a1[0] += __ldg(g_u + (size_t)r1 * F + cl);
                a2[0] += __ldg(g_u + (size_t)r2 * F + cl);
                a3[0] += __ldg(g_u + (size_t)r3 * F + cl);
            }
        }
        for (; i < m; i++) {
            int r0 = __shfl_sync(mask, rp, sub * LPN + i);
            if constexpr (VPL == 2) {
                float2 v0 = __ldg((const float2*)g_u + (size_t)r0 * 32 + cl);
                a0[0] += v0.x; a0[1] += v0.y;
            } else {
                a0[0] += __ldg(g_u + (size_t)r0 * F + cl);
            }
        }
    }

    const float s = g_dinv[node];
    float* outp = (LAYER == 1) ? g_f1 : (LAYER == 2 ? g_f2 : g_f3);

    if constexpr (VPL == 2) {
        float2 us = ((const float2*)g_u)[(size_t)node * 32 + cl];
        float2 bb = __ldg((const float2*)b + cl);
        float2 r;
        r.x = fmaxf(fmaf(s, a0[0] + a1[0] + a2[0] + a3[0] + us.x, bb.x), 0.f);
        r.y = fmaxf(fmaf(s, a0[1] + a1[1] + a2[1] + a3[1] + us.y, bb.y), 0.f);
        ((float2*)outp)[(size_t)node * 32 + cl] = r;
    } else {
        float us = g_u[(size_t)node * F + cl];
        float bb = __ldg(b + cl);
        outp[(size_t)node * F + cl] =
            fmaxf(fmaf(s, a0[0] + a1[0] + a2[0] + a3[0] + us, bb), 0.f);
    }
}

// ---------------- head: out = relu([f1|f2|f3] @ Wfc + bfc) ----------------
__global__ void __launch_bounds__(256) k_head(const float* __restrict__ Wfc,
                                              const float* __restrict__ bfc,
                                              float* __restrict__ out)
{
    __shared__ float wsh[112 * 16];
    __shared__ float fs [16 * 112];
    __shared__ float bs [16];

    const int tid   = threadIdx.x;
    const int node0 = blockIdx.x * 16;

    for (int i = tid; i < 112 * 16; i += 256) wsh[i] = Wfc[i];
    if (tid < 16) bs[tid] = bfc[tid];

    for (int i = tid; i < 16 * 64; i += 256) {
        int ln = i >> 6, k = i & 63; int n = node0 + ln;
        fs[ln * 112 + k] = (n < N_NODES) ? g_f1[(size_t)n * 64 + k] : 0.f;
    }
    for (int i = tid; i < 16 * 32; i += 256) {
        int ln = i >> 5, k = i & 31; int n = node0 + ln;
        fs[ln * 112 + 64 + k] = (n < N_NODES) ? g_f2[(size_t)n * 32 + k] : 0.f;
    }
    for (int i = tid; i < 16 * 16; i += 256) {
        int ln = i >> 4, k = i & 15; int n = node0 + ln;
        fs[ln * 112 + 96 + k] = (n < N_NODES) ? g_f3[(size_t)n * 16 + k] : 0.f;
    }
    __syncthreads();

    const int ln = tid >> 4, j = tid & 15;
    float acc = bs[j];
#pragma unroll
    for (int k = 0; k < 112; k++)
        acc = fmaf(fs[ln * 112 + k], wsh[k * 16 + j], acc);

    int n = node0 + ln;
    if (n < N_NODES) out[(size_t)n * 16 + j] = fmaxf(acc, 0.f);
}

// ---------------- launch ----------------
extern "C" void kernel_launch(void* const* d_in, const int* in_sizes, int n_in,
                              void* d_out, int out_size)
{
    const int*   edges = (const int*)d_in[0];
    const float* feats = (const float*)d_in[1];
    const float* W1    = (const float*)d_in[2];
    const float* b1    = (const float*)d_in[3];
    const float* W2    = (const float*)d_in[4];
    const float* b2    = (const float*)d_in[5];
    const float* W3    = (const float*)d_in[6];
    const float* b3    = (const float*)d_in[7];
    const float* Wfc   = (const float*)d_in[8];
    const float* bfc   = (const float*)d_in[9];
    float* out = (float*)d_out;

    const int E   = in_sizes[0] / 2;
    const int* row = edges;
    const int* col = edges + E;

    // CSR build + dinv
    k_zero_deg  <<<cdiv(N_NODES, 256), 256>>>();
    k_count_deg <<<cdiv(E, 256), 256>>>(col, E);
    k_scan_block<<<NB_SCAN, 1024>>>();
    k_scan_tops <<<1, 128>>>();
    k_scan_final<<<cdiv(N_NODES, 256), 256>>>(E);
    k_csr_fill  <<<cdiv(E, 256), 256>>>(row, col, E);

    const int gemm_grid = cdiv(N_NODES, 64);

    // layer 1: 128 -> 64
    k_gemm<128, 64, 1><<<gemm_grid, 256>>>(feats, W1);
    k_gather<64, 1><<<cdiv(N_NODES, 8), 256>>>(b1);

    // layer 2: 64 -> 32
    k_gemm<64, 32, 2><<<gemm_grid, 256>>>(nullptr, W2);
    k_gather<32, 2><<<cdiv(N_NODES, 8), 256>>>(b2);

    // layer 3: 32 -> 16
    k_gemm<32, 16, 3><<<gemm_grid, 256>>>(nullptr, W3);
    k_gather<16, 3><<<cdiv(N_NODES, 16), 256>>>(b3);

    // dense head
    k_head<<<cdiv(N_NODES, 16), 256>>>(Wfc, bfc, out);
}

// round 3
// speedup vs baseline: 1.6772x; 1.1828x over previous
#include <cuda_runtime.h>
#include <cstdint>

#define N_NODES 100000
#define MAX_E   3200000
#define NB_SCAN ((N_NODES + 1023) / 1024)   // 98

// ---------------- scratch (static device globals) ----------------
__device__ int   g_deg [N_NODES];
__device__ int   g_scan[N_NODES];
__device__ int   g_bsum[NB_SCAN];
__device__ int   g_bpre[NB_SCAN];
__device__ int   g_offs[N_NODES + 1];
__device__ int   g_cur [N_NODES];
__device__ int   g_srow[MAX_E];            // row indices sorted by col (CSR)
__device__ float g_dinv[N_NODES];
__device__ float g_u  [N_NODES * 64];      // (X@W) * dinv[node]
__device__ float g_f1 [N_NODES * 64];
__device__ float g_f2 [N_NODES * 32];
__device__ float g_f3 [N_NODES * 16];

static inline int cdiv(long long a, long long b) { return (int)((a + b - 1) / b); }

// ---------------- packed f32x2 helpers (Blackwell FFMA2 path) ----------------
__device__ __forceinline__ unsigned long long pack2(float lo, float hi)
{
    unsigned long long r;
    asm("mov.b64 %0, {%1, %2};" : "=l"(r) : "f"(lo), "f"(hi));
    return r;
}
__device__ __forceinline__ void ffma2(unsigned long long& d,
                                      unsigned long long a,
                                      unsigned long long b)
{
    asm("fma.rn.f32x2 %0, %1, %2, %0;" : "+l"(d) : "l"(a), "l"(b));
}
__device__ __forceinline__ float2 unpack2(unsigned long long v)
{
    float2 r;
    asm("mov.b64 {%0, %1}, %2;" : "=f"(r.x), "=f"(r.y) : "l"(v));
    return r;
}

// ---------------- degree ----------------
__global__ void k_zero_deg()
{
    int i = blockIdx.x * blockDim.x + threadIdx.x;
    if (i < N_NODES) g_deg[i] = 0;
}

__global__ void k_count_deg(const int* __restrict__ col, int E)
{
    int e = blockIdx.x * blockDim.x + threadIdx.x;
    if (e < E) atomicAdd(&g_deg[col[e]], 1);
}

// ---------------- exclusive scan of degrees -> CSR offsets ----------------
__global__ void __launch_bounds__(1024) k_scan_block()
{
    __shared__ int s[1024];
    int i = blockIdx.x * 1024 + threadIdx.x;
    int v = (i < N_NODES) ? g_deg[i] : 0;
    s[threadIdx.x] = v;
    __syncthreads();
#pragma unroll
    for (int off = 1; off < 1024; off <<= 1) {
        int t = (threadIdx.x >= off) ? s[threadIdx.x - off] : 0;
        __syncthreads();
        s[threadIdx.x] += t;
        __syncthreads();
    }
    if (i < N_NODES) g_scan[i] = s[threadIdx.x];
    if (threadIdx.x == 1023) g_bsum[blockIdx.x] = s[1023];
}

__global__ void __launch_bounds__(128) k_scan_tops()
{
    __shared__ int s[128];
    int tid = threadIdx.x;
    int v = (tid < NB_SCAN) ? g_bsum[tid] : 0;
    s[tid] = v;
    __syncthreads();
#pragma unroll
    for (int off = 1; off < 128; off <<= 1) {
        int t = (tid >= off) ? s[tid - off] : 0;
        __syncthreads();
        s[tid] += t;
        __syncthreads();
    }
    if (tid < NB_SCAN) g_bpre[tid] = s[tid] - v;   // exclusive
}

__global__ void k_scan_final(int E)
{
    int i = blockIdx.x * blockDim.x + threadIdx.x;
    if (i >= N_NODES) return;
    int d    = g_deg[i];
    int excl = g_scan[i] - d + g_bpre[i >> 10];
    g_offs[i] = excl;
    g_cur [i] = excl;
    g_dinv[i] = rsqrtf((float)(d + 1));            // +1 self loop
    if (i == N_NODES - 1) g_offs[N_NODES] = excl + d;
}

__global__ void k_csr_fill(const int* __restrict__ row, const int* __restrict__ col, int E)
{
    int e = blockIdx.x * blockDim.x + threadIdx.x;
    if (e < E) {
        int pos = atomicAdd(&g_cur[col[e]], 1);
        g_srow[pos] = row[e];
    }
}

// ---------------- GEMM: u = (X @ W) * dinv[node]  (FFMA2 inner loop) ----------------
// BN=128 nodes/block, 256 threads; thread tile = 8 nodes (4 packed pairs) x TN outputs.
template<int K, int F, int LAYER>
__global__ void __launch_bounds__(256) k_gemm(const float* __restrict__ Xp,
                                              const float* __restrict__ W)
{
    constexpr int BN   = 128;
    constexpr int BK   = 32;
    constexpr int TN   = F / 16;          // 4, 2, 1
    constexpr int XPAD = BN + 4;          // 132 floats: 528B rows, 16B-aligned

    __shared__ __align__(16) float xs[BK * XPAD];
    __shared__ __align__(16) float ws[BK * F];

    const float* X = (LAYER == 1) ? Xp : (LAYER == 2 ? g_f1 : g_f2);

    const int tid   = threadIdx.x;
    const int node0 = blockIdx.x * BN;
    const int tn    = tid & 15;
    const int tm    = tid >> 4;
    const int nloc  = tm * 8;
    const int ob    = tn * TN;

    unsigned long long acc[4][TN];
#pragma unroll
    for (int p = 0; p < 4; p++)
#pragma unroll
        for (int j = 0; j < TN; j++) acc[p][j] = 0ull;

    for (int kc = 0; kc < K; kc += BK) {
        // stage W chunk (contiguous rows kc..kc+BK)
        for (int i = tid; i < BK * F / 4; i += 256)
            ((float4*)ws)[i] = ((const float4*)(W + (size_t)kc * F))[i];
        // stage X tile transposed: xs[k][node]; float4 loads along k
        for (int t = tid; t < BN * (BK / 4); t += 256) {
            int r  = t >> 3;                 // BK/4 == 8
            int c4 = t & 7;
            int nr = node0 + r;
            float4 v = (nr < N_NODES)
                ? *(const float4*)&X[(size_t)nr * K + kc + c4 * 4]
                : make_float4(0.f, 0.f, 0.f, 0.f);
            xs[(c4 * 4 + 0) * XPAD + r] = v.x;
            xs[(c4 * 4 + 1) * XPAD + r] = v.y;
            xs[(c4 * 4 + 2) * XPAD + r] = v.z;
            xs[(c4 * 4 + 3) * XPAD + r] = v.w;
        }
        __syncthreads();

#pragma unroll 8
        for (int k = 0; k < BK; k++) {
            const unsigned long long* xr =
                (const unsigned long long*)&xs[k * XPAD + nloc];
            unsigned long long x0 = xr[0], x1 = xr[1], x2 = xr[2], x3 = xr[3];

            if constexpr (TN == 4) {
                float4 wv = *(const float4*)&ws[k * F + ob];
                float wj[4] = {wv.x, wv.y, wv.z, wv.w};
#pragma unroll
                for (int j = 0; j < 4; j++) {
                    unsigned long long wp = pack2(wj[j], wj[j]);
                    ffma2(acc[0][j], x0, wp);
                    ffma2(acc[1][j], x1, wp);
                    ffma2(acc[2][j], x2, wp);
                    ffma2(acc[3][j], x3, wp);
                }
            } else if constexpr (TN == 2) {
                float2 wv = *(const float2*)&ws[k * F + ob];
                float wj[2] = {wv.x, wv.y};
#pragma unroll
                for (int j = 0; j < 2; j++) {
                    unsigned long long wp = pack2(wj[j], wj[j]);
                    ffma2(acc[0][j], x0, wp);
                    ffma2(acc[1][j], x1, wp);
                    ffma2(acc[2][j], x2, wp);
                    ffma2(acc[3][j], x3, wp);
                }
            } else {
                float w = ws[k * F + ob];
                unsigned long long wp = pack2(w, w);
                ffma2(acc[0][0], x0, wp);
                ffma2(acc[1][0], x1, wp);
                ffma2(acc[2][0], x2, wp);
                ffma2(acc[3][0], x3, wp);
            }
        }
        __syncthreads();
    }

    // epilogue: scale by dinv[node], store vectorized
#pragma unroll
    for (int p = 0; p < 4; p++) {
        int n0 = node0 + nloc + 2 * p;
        int n1 = n0 + 1;
        float2 a[TN];
#pragma unroll
        for (int j = 0; j < TN; j++) a[j] = unpack2(acc[p][j]);

        if constexpr (TN == 4) {
            if (n0 < N_NODES) {
                float d0 = g_dinv[n0];
                float4 o = make_float4(a[0].x * d0, a[1].x * d0, a[2].x * d0, a[3].x * d0);
                *(float4*)&g_u[(size_t)n0 * F + ob] = o;
            }
            if (n1 < N_NODES) {
                float d1 = g_dinv[n1];
                float4 o = make_float4(a[0].y * d1, a[1].y * d1, a[2].y * d1, a[3].y * d1);
                *(float4*)&g_u[(size_t)n1 * F + ob] = o;
            }
        } else if constexpr (TN == 2) {
            if (n0 < N_NODES) {
                float d0 = g_dinv[n0];
                float2 o = make_float2(a[0].x * d0, a[1].x * d0);
                *(float2*)&g_u[(size_t)n0 * F + ob] = o;
            }
            if (n1 < N_NODES) {
                float d1 = g_dinv[n1];
                float2 o = make_float2(a[0].y * d1, a[1].y * d1);
                *(float2*)&g_u[(size_t)n1 * F + ob] = o;
            }
        } else {
            if (n0 < N_NODES) g_u[(size_t)n0 * F + ob] = a[0].x * g_dinv[n0];
            if (n1 < N_NODES) g_u[(size_t)n1 * F + ob] = a[0].y * g_dinv[n1];
        }
    }
}

// ---------------- fused gather + finalize: f = relu(dinv*(sum_nb u + u_self) + b) ----------------
// float4 lanes: LPN = F/4 lanes per node, NPW = 32/LPN nodes per warp.
template<int F, int LAYER>
__global__ void __launch_bounds__(256) k_gather(const float* __restrict__ b)
{
    constexpr int LPN = F / 4;               // 16, 8, 4
    constexpr int NPW = 32 / LPN;            // 2, 4, 8

    const int warp = (blockIdx.x * blockDim.x + threadIdx.x) >> 5;
    const int lane = threadIdx.x & 31;
    const int sub  = lane / LPN;
    const int cl   = lane - sub * LPN;       // float4 index within row
    const int node = warp * NPW + sub;
    if (node >= N_NODES) return;

    const unsigned mask = ((LPN == 32) ? 0xffffffffu : ((1u << LPN) - 1u)) << (sub * LPN);
    const int start = g_offs[node];
    const int end   = g_offs[node + 1];

    const float4* up = (const float4*)g_u;

    float4 a0 = make_float4(0.f, 0.f, 0.f, 0.f);
    float4 a1 = a0, a2 = a0, a3 = a0;

    for (int base = start; base < end; base += LPN) {
        const int m = min(LPN, end - base);
        int rp = (cl < m) ? __ldg(g_srow + base + cl) : 0;

        int i = 0;
        for (; i + 4 <= m; i += 4) {
            int r0 = __shfl_sync(mask, rp, sub * LPN + i + 0);
            int r1 = __shfl_sync(mask, rp, sub * LPN + i + 1);
            int r2 = __shfl_sync(mask, rp, sub * LPN + i + 2);
            int r3 = __shfl_sync(mask, rp, sub * LPN + i + 3);
            float4 v0 = __ldg(up + (size_t)r0 * LPN + cl);
            float4 v1 = __ldg(up + (size_t)r1 * LPN + cl);
            float4 v2 = __ldg(up + (size_t)r2 * LPN + cl);
            float4 v3 = __ldg(up + (size_t)r3 * LPN + cl);
            a0.x += v0.x; a0.y += v0.y; a0.z += v0.z; a0.w += v0.w;
            a1.x += v1.x; a1.y += v1.y; a1.z += v1.z; a1.w += v1.w;
            a2.x += v2.x; a2.y += v2.y; a2.z += v2.z; a2.w += v2.w;
            a3.x += v3.x; a3.y += v3.y; a3.z += v3.z; a3.w += v3.w;
        }
        for (; i < m; i++) {
            int r0 = __shfl_sync(mask, rp, sub * LPN + i);
            float4 v0 = __ldg(up + (size_t)r0 * LPN + cl);
            a0.x += v0.x; a0.y += v0.y; a0.z += v0.z; a0.w += v0.w;
        }
    }

    const float s = g_dinv[node];
    float* outp = (LAYER == 1) ? g_f1 : (LAYER == 2 ? g_f2 : g_f3);

    float4 us = up[(size_t)node * LPN + cl];
    float4 bb = __ldg((const float4*)b + cl);
    float4 r;
    r.x = fmaxf(fmaf(s, a0.x + a1.x + a2.x + a3.x + us.x, bb.x), 0.f);
    r.y = fmaxf(fmaf(s, a0.y + a1.y + a2.y + a3.y + us.y, bb.y), 0.f);
    r.z = fmaxf(fmaf(s, a0.z + a1.z + a2.z + a3.z + us.z, bb.z), 0.f);
    r.w = fmaxf(fmaf(s, a0.w + a1.w + a2.w + a3.w + us.w, bb.w), 0.f);
    ((float4*)outp)[(size_t)node * LPN + cl] = r;
}

// ---------------- head: out = relu([f1|f2|f3] @ Wfc + bfc) ----------------
__global__ void __launch_bounds__(256) k_head(const float* __restrict__ Wfc,
                                              const float* __restrict__ bfc,
                                              float* __restrict__ out)
{
    __shared__ float wsh[112 * 16];
    __shared__ float fs [16 * 112];
    __shared__ float bs [16];

    const int tid   = threadIdx.x;
    const int node0 = blockIdx.x * 16;

    for (int i = tid; i < 112 * 16; i += 256) wsh[i] = Wfc[i];
    if (tid < 16) bs[tid] = bfc[tid];

    for (int i = tid; i < 16 * 64; i += 256) {
        int ln = i >> 6, k = i & 63; int n = node0 + ln;
        fs[ln * 112 + k] = (n < N_NODES) ? g_f1[(size_t)n * 64 + k] : 0.f;
    }
    for (int i = tid; i < 16 * 32; i += 256) {
        int ln = i >> 5, k = i & 31; int n = node0 + ln;
        fs[ln * 112 + 64 + k] = (n < N_NODES) ? g_f2[(size_t)n * 32 + k] : 0.f;
    }
    for (int i = tid; i < 16 * 16; i += 256) {
        int ln = i >> 4, k = i & 15; int n = node0 + ln;
        fs[ln * 112 + 96 + k] = (n < N_NODES) ? g_f3[(size_t)n * 16 + k] : 0.f;
    }
    __syncthreads();

    const int ln = tid >> 4, j = tid & 15;
    float acc = bs[j];
#pragma unroll
    for (int k = 0; k < 112; k++)
        acc = fmaf(fs[ln * 112 + k], wsh[k * 16 + j], acc);

    int n = node0 + ln;
    if (n < N_NODES) out[(size_t)n * 16 + j] = fmaxf(acc, 0.f);
}

// ---------------- launch ----------------
extern "C" void kernel_launch(void* const* d_in, const int* in_sizes, int n_in,
                              void* d_out, int out_size)
{
    const int*   edges = (const int*)d_in[0];
    const float* feats = (const float*)d_in[1];
    const float* W1    = (const float*)d_in[2];
    const float* b1    = (const float*)d_in[3];
    const float* W2    = (const float*)d_in[4];
    const float* b2    = (const float*)d_in[5];
    const float* W3    = (const float*)d_in[6];
    const float* b3    = (const float*)d_in[7];
    const float* Wfc   = (const float*)d_in[8];
    const float* bfc   = (const float*)d_in[9];
    float* out = (float*)d_out;

    const int E   = in_sizes[0] / 2;
    const int* row = edges;
    const int* col = edges + E;

    // CSR build + dinv
    k_zero_deg  <<<cdiv(N_NODES, 256), 256>>>();
    k_count_deg <<<cdiv(E, 256), 256>>>(col, E);
    k_scan_block<<<NB_SCAN, 1024>>>();
    k_scan_tops <<<1, 128>>>();
    k_scan_final<<<cdiv(N_NODES, 256), 256>>>(E);
    k_csr_fill  <<<cdiv(E, 256), 256>>>(row, col, E);

    const int gemm_grid = cdiv(N_NODES, 128);

    // layer 1: 128 -> 64   (gather: 2 nodes/warp -> 16 nodes/block)
    k_gemm<128, 64, 1><<<gemm_grid, 256>>>(feats, W1);
    k_gather<64, 1><<<cdiv(N_NODES, 16), 256>>>(b1);

    // layer 2: 64 -> 32    (4 nodes/warp -> 32 nodes/block)
    k_gemm<64, 32, 2><<<gemm_grid, 256>>>(nullptr, W2);
    k_gather<32, 2><<<cdiv(N_NODES, 32), 256>>>(b2);

    // layer 3: 32 -> 16    (8 nodes/warp -> 64 nodes/block)
    k_gemm<32, 16, 3><<<gemm_grid, 256>>>(nullptr, W3);
    k_gather<16, 3><<<cdiv(N_NODES, 64), 256>>>(b3);

    // dense head
    k_head<<<cdiv(N_NODES, 16), 256>>>(Wfc, bfc, out);
}